// round 3
// baseline (speedup 1.0000x reference)
#include <cuda_runtime.h>
#include <cuda_bf16.h>
#include <cstdint>

// ---- problem constants ----
#define Bq   4
#define Tq   1024
#define Eq   512
#define Hq   8
#define HDq  64
#define NBq  5
#define VOC  32000
#define MROWS (Bq*Tq)          // 4096

// ---- scratch (device globals; no allocations allowed) ----
__device__ float g_h1 [MROWS*Eq];
__device__ float g_h2 [MROWS*Eq];
__device__ float g_hn [MROWS*Eq];
__device__ float g_k  [MROWS*Eq];
__device__ float g_q  [MROWS*Eq];
__device__ float g_mha[MROWS*Eq];
__device__ float g_wkr[NBq*Eq*Eq];
__device__ float g_wqr[NBq*Eq*Eq];

// ============================================================
// repack Wk/Wq: [NB,H,E,HD] -> [NB,E,H*HD]  (row-major B matrix)
// ============================================================
__global__ void repack_kernel(const float* __restrict__ in, float* __restrict__ out)
{
    int tid = blockIdx.x * blockDim.x + threadIdx.x;   // NB*H*E*16 threads
    if (tid >= NBq * Hq * Eq * 16) return;
    int o4 = tid & 15;
    int e  = (tid >> 4) & 511;
    int h  = (tid >> 13) & 7;
    int i  = tid >> 16;
    float4 v = *(const float4*)(in  + ((((size_t)i*Hq + h)*Eq + e)*HDq + o4*4));
    *(float4*)(out + (((size_t)i*Eq + e)*Eq + h*HDq + o4*4)) = v;
}

// ============================================================
// embedding: h[b,t,:] = tok_emb[x[b,t],:] + pos_emb[t,:]
// one block per token row, 128 threads, float4
// ============================================================
__global__ void embed_kernel(const int* __restrict__ x,
                             const float* __restrict__ tok,
                             const float* __restrict__ pos,
                             float* __restrict__ h)
{
    int row = blockIdx.x;              // b*T + t
    int t   = row & (Tq - 1);
    int idx = x[row];
    int tid = threadIdx.x;             // 0..127
    float4 a = ((const float4*)(tok + (size_t)idx * Eq))[tid];
    float4 p = ((const float4*)(pos + (size_t)t   * Eq))[tid];
    float4 o; o.x = a.x+p.x; o.y = a.y+p.y; o.z = a.z+p.z; o.w = a.w+p.w;
    ((float4*)(h + (size_t)row * Eq))[tid] = o;
}

// ============================================================
// layernorm: one block per row (512 floats), 128 threads
// ============================================================
__global__ void ln_kernel(const float* __restrict__ in,
                          const float* __restrict__ g,
                          const float* __restrict__ b,
                          float* __restrict__ out)
{
    int row = blockIdx.x, tid = threadIdx.x;
    float4 v = ((const float4*)(in + (size_t)row * Eq))[tid];
    float s  = v.x + v.y + v.z + v.w;
    float sq = v.x*v.x + v.y*v.y + v.z*v.z + v.w*v.w;
    #pragma unroll
    for (int o = 16; o; o >>= 1) {
        s  += __shfl_xor_sync(0xffffffffu, s,  o);
        sq += __shfl_xor_sync(0xffffffffu, sq, o);
    }
    __shared__ float sm[4], sm2[4];
    int wid = tid >> 5, lane = tid & 31;
    if (lane == 0) { sm[wid] = s; sm2[wid] = sq; }
    __syncthreads();
    s  = sm[0] + sm[1] + sm[2] + sm[3];
    sq = sm2[0] + sm2[1] + sm2[2] + sm2[3];
    float mu   = s * (1.0f / Eq);
    float var  = sq * (1.0f / Eq) - mu * mu;
    float rstd = rsqrtf(var + 1e-5f);
    float4 gv = ((const float4*)g)[tid];
    float4 bv = ((const float4*)b)[tid];
    float4 o;
    o.x = (v.x - mu) * rstd * gv.x + bv.x;
    o.y = (v.y - mu) * rstd * gv.y + bv.y;
    o.z = (v.z - mu) * rstd * gv.z + bv.z;
    o.w = (v.w - mu) * rstd * gv.w + bv.w;
    ((float4*)(out + (size_t)row * Eq))[tid] = o;
}

// ============================================================
// SGEMM: C[M,N] = A[M,K] @ B[K,N]  (+bias, +relu, +resid)
// 128x128 block tile, BK=8, 256 threads, 8x8 per thread
// Requires M%128==0, N%128==0, K%8==0, 16B-aligned pointers.
// epilogue: v = A@B (+bias[col]); if RELU v=max(v,0); if RESID v+=resid[r,c]
// ============================================================
template<bool BIAS, bool RELU, bool RESID>
__global__ __launch_bounds__(256) void sgemm(
    const float* __restrict__ A, const float* __restrict__ B,
    const float* __restrict__ bias, const float* __restrict__ resid,
    float* __restrict__ C, int M, int N, int K)
{
    __shared__ float As[8][128];
    __shared__ float Bs[8][128];
    int tid = threadIdx.x;
    int m0 = blockIdx.y * 128;
    int n0 = blockIdx.x * 128;
    int tx = tid & 15, ty = tid >> 4;

    int a_row = tid >> 1, a_kq = (tid & 1) * 4;
    int b_k   = tid >> 5, b_n  = (tid & 31) * 4;

    const float* Aptr = A + (size_t)(m0 + a_row) * K + a_kq;
    const float* Bptr = B + (size_t)b_k * N + n0 + b_n;

    float4 a_reg = *(const float4*)Aptr;
    float4 b_reg = *(const float4*)Bptr;

    float acc[8][8];
    #pragma unroll
    for (int i = 0; i < 8; i++)
        #pragma unroll
        for (int j = 0; j < 8; j++) acc[i][j] = 0.0f;

    int KT = K >> 3;
    for (int kt = 0; kt < KT; kt++) {
        As[a_kq + 0][a_row] = a_reg.x;
        As[a_kq + 1][a_row] = a_reg.y;
        As[a_kq + 2][a_row] = a_reg.z;
        As[a_kq + 3][a_row] = a_reg.w;
        *(float4*)&Bs[b_k][b_n] = b_reg;
        __syncthreads();
        if (kt + 1 < KT) {
            a_reg = *(const float4*)(Aptr + (size_t)(kt + 1) * 8);
            b_reg = *(const float4*)(Bptr + (size_t)(kt + 1) * 8 * N);
        }
        #pragma unroll
        for (int k = 0; k < 8; k++) {
            float4 a0 = *(const float4*)&As[k][ty * 4];
            float4 a1 = *(const float4*)&As[k][64 + ty * 4];
            float4 b0 = *(const float4*)&Bs[k][tx * 4];
            float4 b1 = *(const float4*)&Bs[k][64 + tx * 4];
            float av[8] = {a0.x, a0.y, a0.z, a0.w, a1.x, a1.y, a1.z, a1.w};
            float bv[8] = {b0.x, b0.y, b0.z, b0.w, b1.x, b1.y, b1.z, b1.w};
            #pragma unroll
            for (int i = 0; i < 8; i++)
                #pragma unroll
                for (int j = 0; j < 8; j++)
                    acc[i][j] = fmaf(av[i], bv[j], acc[i][j]);
        }
        __syncthreads();
    }

    #pragma unroll
    for (int i = 0; i < 8; i++) {
        int r = m0 + ((i < 4) ? (ty * 4 + i) : (64 + ty * 4 + i - 4));
        #pragma unroll
        for (int jb = 0; jb < 2; jb++) {
            int c = n0 + jb * 64 + tx * 4;
            float4 v;
            v.x = acc[i][jb * 4 + 0];
            v.y = acc[i][jb * 4 + 1];
            v.z = acc[i][jb * 4 + 2];
            v.w = acc[i][jb * 4 + 3];
            if (BIAS) {
                float4 bb = *(const float4*)(bias + c);
                v.x += bb.x; v.y += bb.y; v.z += bb.z; v.w += bb.w;
            }
            if (RELU) {
                v.x = fmaxf(v.x, 0.0f); v.y = fmaxf(v.y, 0.0f);
                v.z = fmaxf(v.z, 0.0f); v.w = fmaxf(v.w, 0.0f);
            }
            if (RESID) {
                float4 rr = *(const float4*)(resid + (size_t)r * N + c);
                v.x += rr.x; v.y += rr.y; v.z += rr.z; v.w += rr.w;
            }
            *(float4*)(C + (size_t)r * N + c) = v;
        }
    }
}

// ============================================================
// fused causal attention with the reference's quirks:
//   scores[t,s] = (k[t] . q[s]) * E^-0.5 ,  v == q
// K,Q,O all in [B,T, H*HD] layout (head-major inner).
// grid: (T/8, B*H), 256 threads = 8 warps, warp = one query row.
// q-tiles (128 rows x 64) staged in SMEM, online softmax.
// ============================================================
__global__ __launch_bounds__(256) void attn_kernel(
    const float* __restrict__ K, const float* __restrict__ Q,
    float* __restrict__ O)
{
    __shared__ float qs[128][64];
    int bh = blockIdx.y;
    int b = bh >> 3, h = bh & 7;
    int wid = threadIdx.x >> 5, lane = threadIdx.x & 31;
    int t = blockIdx.x * 8 + wid;
    const float scale = 0.044194173824159216f;   // 512^-0.5 (E, not HD!)

    size_t kbase = ((size_t)(b * Tq + t)) * Eq + h * HDq;
    float k0 = K[kbase + lane] * scale;
    float k1 = K[kbase + lane + 32] * scale;

    float m = -1e30f, l = 0.0f, acc0 = 0.0f, acc1 = 0.0f;
    int tmax = blockIdx.x * 8 + 7;

    for (int s0 = 0; s0 <= tmax; s0 += 128) {
        // cooperative load of 128 q rows
        #pragma unroll
        for (int it = 0; it < 8; it++) {
            int idx = it * 256 + threadIdx.x;
            int r = idx >> 4, d4 = (idx & 15) * 4;
            *(float4*)&qs[r][d4] =
                *(const float4*)&Q[((size_t)(b * Tq + s0 + r)) * Eq + h * HDq + d4];
        }
        __syncthreads();

        int send = min(127, t - s0);
        for (int si = 0; si <= send; si++) {
            float q0 = qs[si][lane];
            float q1 = qs[si][lane + 32];
            float p = fmaf(k0, q0, k1 * q1);
            p += __shfl_xor_sync(0xffffffffu, p, 16);
            p += __shfl_xor_sync(0xffffffffu, p, 8);
            p += __shfl_xor_sync(0xffffffffu, p, 4);
            p += __shfl_xor_sync(0xffffffffu, p, 2);
            p += __shfl_xor_sync(0xffffffffu, p, 1);
            float mn = fmaxf(m, p);
            float alpha = __expf(m - mn);
            float w = __expf(p - mn);
            l    = fmaf(l,    alpha, w);
            acc0 = fmaf(acc0, alpha, w * q0);
            acc1 = fmaf(acc1, alpha, w * q1);
            m = mn;
        }
        __syncthreads();
    }
    float inv = 1.0f / l;
    O[kbase + lane]      = acc0 * inv;
    O[kbase + lane + 32] = acc1 * inv;
}

// ============================================================
// launch
// ============================================================
extern "C" void kernel_launch(void* const* d_in, const int* in_sizes, int n_in,
                              void* d_out, int out_size)
{
    const int*   x     = (const int*)  d_in[0];
    const float* tok   = (const float*)d_in[1];
    const float* pos   = (const float*)d_in[2];
    const float* Wk    = (const float*)d_in[3];
    const float* Wq    = (const float*)d_in[4];
    const float* Wres  = (const float*)d_in[5];
    const float* ln1g  = (const float*)d_in[6];
    const float* ln1b  = (const float*)d_in[7];
    const float* mlpW  = (const float*)d_in[8];
    const float* mlpb  = (const float*)d_in[9];
    const float* ln2g  = (const float*)d_in[10];
    const float* ln2b  = (const float*)d_in[11];
    const float* lnfg  = (const float*)d_in[12];
    const float* lnfb  = (const float*)d_in[13];
    const float* projW = (const float*)d_in[14];
    const float* projb = (const float*)d_in[15];
    float* out = (float*)d_out;

    float *h1, *h2, *hn, *kb, *qb, *mha, *wkr, *wqr;
    cudaGetSymbolAddress((void**)&h1,  g_h1);
    cudaGetSymbolAddress((void**)&h2,  g_h2);
    cudaGetSymbolAddress((void**)&hn,  g_hn);
    cudaGetSymbolAddress((void**)&kb,  g_k);
    cudaGetSymbolAddress((void**)&qb,  g_q);
    cudaGetSymbolAddress((void**)&mha, g_mha);
    cudaGetSymbolAddress((void**)&wkr, g_wkr);
    cudaGetSymbolAddress((void**)&wqr, g_wqr);

    repack_kernel<<<1280, 256>>>(Wk, wkr);
    repack_kernel<<<1280, 256>>>(Wq, wqr);
    embed_kernel<<<MROWS, 128>>>(x, tok, pos, h1);

    dim3 ge(Eq / 128, MROWS / 128);          // 4 x 32
    for (int i = 0; i < NBq; i++) {
        const size_t wo = (size_t)i * Eq * Eq;
        ln_kernel<<<MROWS, 128>>>(h1, ln1g + i * Eq, ln1b + i * Eq, hn);
        sgemm<false, false, false><<<ge, 256>>>(hn, wkr + wo, nullptr, nullptr, kb, MROWS, Eq, Eq);
        sgemm<false, false, false><<<ge, 256>>>(hn, wqr + wo, nullptr, nullptr, qb, MROWS, Eq, Eq);
        attn_kernel<<<dim3(Tq / 8, Bq * Hq), 256>>>(kb, qb, mha);
        sgemm<false, false, true><<<ge, 256>>>(h1, Wres + wo, nullptr, mha, h2, MROWS, Eq, Eq);
        ln_kernel<<<MROWS, 128>>>(h2, ln2g + i * Eq, ln2b + i * Eq, hn);
        sgemm<true, true, true><<<ge, 256>>>(hn, mlpW + wo, mlpb + i * Eq, h2, h1, MROWS, Eq, Eq);
    }

    ln_kernel<<<MROWS, 128>>>(h1, lnfg, lnfb, hn);
    sgemm<true, false, false><<<dim3(VOC / 128, MROWS / 128), 256>>>(
        hn, projW, projb, nullptr, out, MROWS, VOC, Eq);
}